// round 1
// baseline (speedup 1.0000x reference)
#include <cuda_runtime.h>
#include <math.h>

// ---------------- problem constants ----------------
#define B_TOTAL   16384
#define NSLOT     32
#define SDIM      64
#define HID       128
#define NKNOWN    9
#define NITER     3

#define PV_OFF    0
#define SLOTS_OFF (B_TOTAL*NKNOWN)                       // 147456
#define FREE_OFF  (B_TOTAL*NKNOWN + B_TOTAL*NSLOT*SDIM)  // 33701888

// scratch: gi[b][192] (upd == v for every slot since attn collapses to exactly 1.0)
__device__ float g_gi[(size_t)B_TOTAL * 192];

__device__ __forceinline__ float sigm_f(float x) { return 1.0f / (1.0f + __expf(-x)); }
__device__ __forceinline__ float gelu_f(float x) { return 0.5f * x * (1.0f + erff(x * 0.70710678118654752440f)); }

// ================= Kernel A: per-batch x -> LN -> v -> gi =================
__global__ void __launch_bounds__(64) kA(
    const float* __restrict__ ws, const float* __restrict__ Wi, const float* __restrict__ bi,
    const float* __restrict__ g_in, const float* __restrict__ b_in,
    const float* __restrict__ Wv, const float* __restrict__ bv,
    const float* __restrict__ Wih, const float* __restrict__ bih)
{
    int b = blockIdx.x, tid = threadIdx.x;
    __shared__ float s_in[256];
    __shared__ float s_x[64];
    __shared__ float s_v[64];
    __shared__ float sred[2];

    const float* wrow = ws + (size_t)b * 256;
    #pragma unroll
    for (int i = tid; i < 256; i += 64) s_in[i] = wrow[i];
    __syncthreads();

    // x[tid] = ws @ Wi + bi   (Wi loads coalesced across threads)
    float acc = bi[tid];
    #pragma unroll 4
    for (int i = 0; i < 256; i++) acc += s_in[i] * Wi[i * 64 + tid];

    // LayerNorm over 64 across the two warps
    float v = acc;
    #pragma unroll
    for (int o = 16; o; o >>= 1) v += __shfl_down_sync(0xffffffffu, v, o);
    if ((tid & 31) == 0) sred[tid >> 5] = v;
    __syncthreads();
    float mu = (sred[0] + sred[1]) * (1.0f / 64.0f);
    __syncthreads();
    float dv = acc - mu;
    float vv = dv * dv;
    #pragma unroll
    for (int o = 16; o; o >>= 1) vv += __shfl_down_sync(0xffffffffu, vv, o);
    if ((tid & 31) == 0) sred[tid >> 5] = vv;
    __syncthreads();
    float var = (sred[0] + sred[1]) * (1.0f / 64.0f);
    float inv = rsqrtf(var + 1e-5f);
    s_x[tid] = dv * inv * g_in[tid] + b_in[tid];
    __syncthreads();

    // v = x @ Wv + bv
    float vacc = bv[tid];
    #pragma unroll 4
    for (int d = 0; d < 64; d++) vacc += s_x[d] * Wv[d * 64 + tid];
    s_v[tid] = vacc;
    __syncthreads();

    // gi = v @ W_ih + b_ih  (192 outputs, 3 per thread)
    #pragma unroll
    for (int j = tid; j < 192; j += 64) {
        float a = bih[j];
        #pragma unroll 4
        for (int d = 0; d < 64; d++) a += s_v[d] * Wih[d * 192 + j];
        g_gi[(size_t)b * 192 + j] = a;
    }
}

// ================= Kernel Z: zero free_act accumulators =================
__global__ void kZ(float* __restrict__ out)
{
    int i = threadIdx.x;
    if (i < NSLOT - NKNOWN) out[FREE_OFF + i] = 0.0f;
}

// ================= Kernel B: fused GRU + MLP iterations + head =================
// block = 256 threads = 8 batch elems x 32 slots (1 thread per slot)
// dynamic smem layout (floats):
//   0      s_whh  12288
//   12288  s_w1    8192
//   20480  s_w2    8192
//   28672  s_bhh    192
//   28864  s_b1     128
//   28992  s_b2      64
//   29056  s_gm      64
//   29120  s_bm      64
//   29184  s_gi    1536
//   30720  s_prev 16640  (256 slots * stride 65, conflict-free)
// total 47360 floats = 189440 B
#define SMEMB_FLOATS 47360

__global__ void __launch_bounds__(256, 1) kB(
    const float* __restrict__ eps, const float* __restrict__ mu0, const float* __restrict__ sg0,
    const float* __restrict__ Whh, const float* __restrict__ bhh,
    const float* __restrict__ W1, const float* __restrict__ b1,
    const float* __restrict__ W2, const float* __restrict__ b2,
    const float* __restrict__ gm, const float* __restrict__ bm,
    const float* __restrict__ Wh1, const float* __restrict__ bh1,
    const float* __restrict__ Wh2, const float* __restrict__ bh2,
    float* __restrict__ out)
{
    extern __shared__ float sm[];
    float* s_whh  = sm;
    float* s_w1   = sm + 12288;
    float* s_w2   = sm + 20480;
    float* s_bhh  = sm + 28672;
    float* s_b1   = sm + 28864;
    float* s_b2   = sm + 28992;
    float* s_gm   = sm + 29056;
    float* s_bm   = sm + 29120;
    float* s_gi   = sm + 29184;
    float* s_prev = sm + 30720;

    int tid = threadIdx.x;

    for (int i = tid; i < 12288 / 4; i += 256) ((float4*)s_whh)[i] = ((const float4*)Whh)[i];
    for (int i = tid; i < 8192 / 4;  i += 256) ((float4*)s_w1)[i]  = ((const float4*)W1)[i];
    for (int i = tid; i < 8192 / 4;  i += 256) ((float4*)s_w2)[i]  = ((const float4*)W2)[i];
    if (tid < 192) s_bhh[tid] = bhh[tid];
    if (tid < 128) s_b1[tid]  = b1[tid];
    if (tid < 64) { s_b2[tid] = b2[tid]; s_gm[tid] = gm[tid]; s_bm[tid] = bm[tid]; }
    {
        const float* gsrc = g_gi + (size_t)blockIdx.x * 8 * 192;
        for (int i = tid; i < 1536; i += 256) s_gi[i] = gsrc[i];
    }

    int bb = tid >> 5, s = tid & 31;
    size_t b = (size_t)blockIdx.x * 8 + bb;
    int pbase = tid * 65;

    // slots init: mu + sigma * eps
    {
        const float4* ep = (const float4*)(eps + (b * NSLOT + s) * SDIM);
        const float4* m4 = (const float4*)(mu0 + (size_t)s * SDIM);
        const float4* g4 = (const float4*)(sg0 + (size_t)s * SDIM);
        #pragma unroll
        for (int q = 0; q < 16; q++) {
            float4 e = ep[q], m = m4[q], sg = g4[q];
            s_prev[pbase + 4 * q + 0] = m.x + sg.x * e.x;
            s_prev[pbase + 4 * q + 1] = m.y + sg.y * e.y;
            s_prev[pbase + 4 * q + 2] = m.z + sg.z * e.z;
            s_prev[pbase + 4 * q + 3] = m.w + sg.w * e.w;
        }
    }
    __syncthreads();

    const float* gi = s_gi + bb * 192;
    float rbuf[64];

    for (int it = 0; it < NITER; ++it) {
        // ---- pass 1: r = sigmoid(gi_r + prev@Whh[:,0:64] + bhh_r) ----
        #pragma unroll
        for (int j = 0; j < 64; j++) rbuf[j] = s_bhh[j] + gi[j];
        #pragma unroll 2
        for (int d = 0; d < 64; d++) {
            float p = s_prev[pbase + d];
            const float4* w = (const float4*)(s_whh + d * 192);
            #pragma unroll
            for (int q = 0; q < 16; q++) {
                float4 ww = w[q];
                rbuf[4 * q + 0] += p * ww.x; rbuf[4 * q + 1] += p * ww.y;
                rbuf[4 * q + 2] += p * ww.z; rbuf[4 * q + 3] += p * ww.w;
            }
        }
        #pragma unroll
        for (int j = 0; j < 64; j++) rbuf[j] = sigm_f(rbuf[j]);

        // ---- pass 2: z, n, new state (in j-chunks of 16; rbuf holds r then new) ----
        #pragma unroll
        for (int jb = 0; jb < 4; jb++) {
            float az[16], an[16];
            #pragma unroll
            for (int jj = 0; jj < 16; jj++) {
                int j = jb * 16 + jj;
                az[jj] = s_bhh[64 + j] + gi[64 + j];
                an[jj] = s_bhh[128 + j];           // gi NOT pre-added: n = tanh(gi_n + r*(dot+bhh_n))
            }
            #pragma unroll 2
            for (int d = 0; d < 64; d++) {
                float p = s_prev[pbase + d];
                const float4* wz = (const float4*)(s_whh + d * 192 + 64 + jb * 16);
                const float4* wn = (const float4*)(s_whh + d * 192 + 128 + jb * 16);
                #pragma unroll
                for (int q = 0; q < 4; q++) {
                    float4 a = wz[q];
                    az[4 * q + 0] += p * a.x; az[4 * q + 1] += p * a.y;
                    az[4 * q + 2] += p * a.z; az[4 * q + 3] += p * a.w;
                    float4 c = wn[q];
                    an[4 * q + 0] += p * c.x; an[4 * q + 1] += p * c.y;
                    an[4 * q + 2] += p * c.z; an[4 * q + 3] += p * c.w;
                }
            }
            #pragma unroll
            for (int jj = 0; jj < 16; jj++) {
                int j = jb * 16 + jj;
                float z = sigm_f(az[jj]);
                float n = tanhf(gi[128 + j] + rbuf[j] * an[jj]);
                float pr = s_prev[pbase + j];
                rbuf[j] = (1.0f - z) * n + z * pr;
            }
        }

        // ---- LayerNorm + MLP residual ----
        float mu = 0.0f;
        #pragma unroll
        for (int j = 0; j < 64; j++) mu += rbuf[j];
        mu *= (1.0f / 64.0f);
        float var = 0.0f;
        #pragma unroll
        for (int j = 0; j < 64; j++) { float d = rbuf[j] - mu; var += d * d; }
        var *= (1.0f / 64.0f);
        float inv = rsqrtf(var + 1e-5f);
        #pragma unroll
        for (int d = 0; d < 64; d++) s_prev[pbase + d] = (rbuf[d] - mu) * inv * s_gm[d] + s_bm[d];
        #pragma unroll
        for (int j = 0; j < 64; j++) rbuf[j] += s_b2[j];

        for (int mb = 0; mb < 8; mb++) {
            float ah[16];
            #pragma unroll
            for (int jj = 0; jj < 16; jj++) ah[jj] = s_b1[mb * 16 + jj];
            #pragma unroll 2
            for (int d = 0; d < 64; d++) {
                float p = s_prev[pbase + d];
                const float4* w = (const float4*)(s_w1 + d * 128 + mb * 16);
                #pragma unroll
                for (int q = 0; q < 4; q++) {
                    float4 a = w[q];
                    ah[4 * q + 0] += p * a.x; ah[4 * q + 1] += p * a.y;
                    ah[4 * q + 2] += p * a.z; ah[4 * q + 3] += p * a.w;
                }
            }
            #pragma unroll
            for (int jj = 0; jj < 16; jj++) {
                float g = gelu_f(ah[jj]);
                const float4* w2 = (const float4*)(s_w2 + (mb * 16 + jj) * 64);
                #pragma unroll
                for (int q = 0; q < 16; q++) {
                    float4 ww = w2[q];
                    rbuf[4 * q + 0] += g * ww.x; rbuf[4 * q + 1] += g * ww.y;
                    rbuf[4 * q + 2] += g * ww.z; rbuf[4 * q + 3] += g * ww.w;
                }
            }
        }
        #pragma unroll
        for (int d = 0; d < 64; d++) s_prev[pbase + d] = rbuf[d];
    }

    // ---- write final slots ----
    {
        float4* o = (float4*)(out + SLOTS_OFF + (b * NSLOT + s) * SDIM);
        #pragma unroll
        for (int q = 0; q < 16; q++)
            o[q] = make_float4(rbuf[4 * q], rbuf[4 * q + 1], rbuf[4 * q + 2], rbuf[4 * q + 3]);
    }

    // ---- head + free_act (reuse weight smem for Wh1 etc.) ----
    __syncthreads();
    float* s_hw1 = sm;           // 18432 (overlaps s_whh + s_w1, both dead now)
    float* s_hb1 = sm + 18432;   // 288
    float* s_hw2 = sm + 18720;   // 288
    float* s_hb2 = sm + 19008;   // 9
    for (int i = tid; i < 18432 / 4; i += 256) ((float4*)s_hw1)[i] = ((const float4*)Wh1)[i];
    for (int i = tid; i < 288; i += 256) { s_hb1[i] = bh1[i]; s_hw2[i] = Wh2[i]; }
    if (tid < 9) s_hb2[tid] = bh2[tid];
    __syncthreads();

    if (s < NKNOWN) {
        int k = s;
        float ha[32];
        #pragma unroll
        for (int h = 0; h < 32; h++) ha[h] = s_hb1[k * 32 + h];
        #pragma unroll 2
        for (int d = 0; d < 64; d++) {
            float p = s_prev[pbase + d];
            const float4* w = (const float4*)(s_hw1 + k * 2048 + d * 32);
            #pragma unroll
            for (int q = 0; q < 8; q++) {
                float4 a = w[q];
                ha[4 * q + 0] += p * a.x; ha[4 * q + 1] += p * a.y;
                ha[4 * q + 2] += p * a.z; ha[4 * q + 3] += p * a.w;
            }
        }
        float a2 = s_hb2[k];
        #pragma unroll
        for (int h = 0; h < 32; h++) a2 += gelu_f(ha[h]) * s_hw2[k * 32 + h];
        out[PV_OFF + b * NKNOWN + k] = sigm_f(a2);
    } else {
        float sq = 0.0f;
        #pragma unroll
        for (int d = 0; d < 64; d++) sq += rbuf[d] * rbuf[d];
        atomicAdd(out + FREE_OFF + (s - NKNOWN), sqrtf(sq) * (1.0f / (float)B_TOTAL));
    }
}

// ================= launch =================
extern "C" void kernel_launch(void* const* d_in, const int* in_sizes, int n_in,
                              void* d_out, int out_size)
{
    const float* ws   = (const float*)d_in[0];
    const float* eps  = (const float*)d_in[1];
    const float* mu0  = (const float*)d_in[2];
    const float* sg0  = (const float*)d_in[3];
    const float* Wi   = (const float*)d_in[4];
    const float* bi   = (const float*)d_in[5];
    // d_in[6..9] = Wk, bk, Wq, bq : mathematically dead (attn == 1.0 exactly)
    const float* Wv   = (const float*)d_in[10];
    const float* bv   = (const float*)d_in[11];
    const float* Wih  = (const float*)d_in[12];
    const float* bih  = (const float*)d_in[13];
    const float* Whh  = (const float*)d_in[14];
    const float* bhh  = (const float*)d_in[15];
    const float* W1   = (const float*)d_in[16];
    const float* b1   = (const float*)d_in[17];
    const float* W2   = (const float*)d_in[18];
    const float* b2   = (const float*)d_in[19];
    const float* g_in = (const float*)d_in[20];
    const float* b_in = (const float*)d_in[21];
    // d_in[22..23] = g_sl, b_sl : dead (slot-LN feeds only q)
    const float* gm   = (const float*)d_in[24];
    const float* bm   = (const float*)d_in[25];
    const float* Wh1  = (const float*)d_in[26];
    const float* bh1  = (const float*)d_in[27];
    const float* Wh2  = (const float*)d_in[28];
    const float* bh2  = (const float*)d_in[29];
    float* out = (float*)d_out;

    size_t smemB = (size_t)SMEMB_FLOATS * sizeof(float);
    cudaFuncSetAttribute(kB, cudaFuncAttributeMaxDynamicSharedMemorySize, (int)smemB);

    kZ<<<1, 32>>>(out);
    kA<<<B_TOTAL, 64>>>(ws, Wi, bi, g_in, b_in, Wv, bv, Wih, bih);
    kB<<<B_TOTAL / 8, 256, smemB>>>(eps, mu0, sg0, Whh, bhh, W1, b1, W2, b2,
                                    gm, bm, Wh1, bh1, Wh2, bh2, out);
}